// round 3
// baseline (speedup 1.0000x reference)
#include <cuda_runtime.h>
#include <cuda_bf16.h>
#include <cstdint>
#include <cstddef>

#define NWSEQ 1024
#define TW    64
#define MWORD (NWSEQ*TW)
#define NDOC  32
#define TSENT 32
#define MSENT (NDOC*TSENT)
#define HD2   512
#define HD3   768
#define EDIM  200

typedef unsigned long long ull;

// scratch (device globals; allocation-free rule)
__device__ float g_xg [2ull*MWORD*HD3];     // word input gates; later reused as rep scratch
__device__ float g_h  [(size_t)MWORD*HD2];  // word BiGRU hidden
__device__ float g_sents[(size_t)MSENT*HD2];
__device__ float g_xg2[2ull*MSENT*HD3];     // sentence input gates; later reused as rep2
__device__ float g_h2 [(size_t)MSENT*HD2];
__device__ float4 g_whp [2*256*256 + 256];  // repacked word Wh  [dir][k][j]{r,z,n,pad} (+prefetch pad)
__device__ float4 g_whp2[2*256*256 + 256];  // repacked sentence Wh

__device__ __forceinline__ ull pk2(float lo, float hi){
    ull r; asm("mov.b64 %0, {%1,%2};" : "=l"(r) : "f"(lo), "f"(hi)); return r;
}
__device__ __forceinline__ float2 upk2(ull v){
    float2 f; asm("mov.b64 {%0,%1}, %2;" : "=f"(f.x), "=f"(f.y) : "l"(v)); return f;
}
// packed f32x2 fma: 2x FFMA throughput on sm_100+ (ptxas never emits from C++)
__device__ __forceinline__ ull fma2(ull a, ull b, ull c){
    ull d; asm("fma.rn.f32x2 %0, %1, %2, %3;" : "=l"(d) : "l"(a), "l"(b), "l"(c)); return d;
}
__device__ __forceinline__ float fsig(float x){ return 1.0f/(1.0f + __expf(-x)); }
__device__ __forceinline__ float ftanh(float x){ return 1.0f - 2.0f/(__expf(2.0f*x) + 1.0f); }

// ---------------------------------------------------------------------------
// Repack Wh [256][768] -> float4[dir][256 k][256 j] = {Wr, Wz, Wn, 0}
// ---------------------------------------------------------------------------
__global__ void repack_wh_kernel(const float* __restrict__ Whf,
                                 const float* __restrict__ Whb,
                                 float4* __restrict__ whp){
    int k = blockIdx.x, d = blockIdx.y, j = threadIdx.x;
    const float* Wh = d ? Whb : Whf;
    float4 v;
    v.x = Wh[(size_t)k*HD3 + j];
    v.y = Wh[(size_t)k*HD3 + 256 + j];
    v.z = Wh[(size_t)k*HD3 + 512 + j];
    v.w = 0.f;
    whp[((size_t)d*256 + k)*256 + j] = v;
}

// ---------------------------------------------------------------------------
// GEMM: out[dir][m][0..N) = A[row(m)][0..K) @ W_dir + bias_dir
// row(m) = gather[m] or m. 128x128 tiles, BK=8, 8x8 micro with f32x2.
// grid = (M/128, 2*nyPerDir or nyPerDir). ldw = nyPerDir*128 (row stride of W & out)
// ---------------------------------------------------------------------------
__global__ __launch_bounds__(256) void gemm128_kernel(
    const float* __restrict__ A, const int* __restrict__ gather, int K,
    const float* __restrict__ Wf, const float* __restrict__ Wb,
    const float* __restrict__ bf, const float* __restrict__ bb,
    float* __restrict__ out, int M, int nyPerDir)
{
    __shared__ __align__(16) float sA[8][132];
    __shared__ __align__(16) float sB[8][128];
    int tid = threadIdx.x;
    int tx = tid & 15, ty = tid >> 4;
    int m0 = blockIdx.x * 128;
    int dir = blockIdx.y / nyPerDir;
    int j0  = (blockIdx.y % nyPerDir) * 128;
    int ldw = nyPerDir * 128;
    const float* W    = dir ? Wb : Wf;
    const float* bias = dir ? bb : bf;

    // A loader: thread covers (kA, mA+32i), i=0..3
    int kA = tid & 7, mA = tid >> 3;
    const float* arow[4];
#pragma unroll
    for (int i = 0; i < 4; i++){
        int r = m0 + mA + 32*i;
        arow[i] = A + (size_t)(gather ? gather[r] : r) * K;
    }
    // B loader: thread covers (kB, jB..jB+3)
    int kB = tid >> 5, jB = (tid & 31) * 4;

    ull acc[8][4];
#pragma unroll
    for (int r = 0; r < 8; r++)
#pragma unroll
        for (int c = 0; c < 4; c++) acc[r][c] = 0ull;

    float ra[4]; float4 rb;
#pragma unroll
    for (int i = 0; i < 4; i++) ra[i] = arow[i][kA];
    rb = *(const float4*)&W[(size_t)kB * ldw + j0 + jB];

    int ntiles = K / 8;
    for (int t = 0; t < ntiles; t++) {
        __syncthreads();
#pragma unroll
        for (int i = 0; i < 4; i++) sA[kA][mA + 32*i] = ra[i];
        *(float4*)&sB[kB][jB] = rb;
        __syncthreads();
        if (t + 1 < ntiles) {
            int k0 = (t + 1) * 8;
#pragma unroll
            for (int i = 0; i < 4; i++) ra[i] = arow[i][k0 + kA];
            rb = *(const float4*)&W[(size_t)(k0 + kB) * ldw + j0 + jB];
        }
#pragma unroll
        for (int kk = 0; kk < 8; kk++){
            float4 a0 = *(const float4*)&sA[kk][ty*8];
            float4 a1 = *(const float4*)&sA[kk][ty*8 + 4];
            ulonglong2 b0 = *(const ulonglong2*)&sB[kk][tx*8];
            ulonglong2 b1 = *(const ulonglong2*)&sB[kk][tx*8 + 4];
            float av[8] = {a0.x,a0.y,a0.z,a0.w,a1.x,a1.y,a1.z,a1.w};
#pragma unroll
            for (int r = 0; r < 8; r++){
                ull as = pk2(av[r], av[r]);
                acc[r][0] = fma2(as, b0.x, acc[r][0]);
                acc[r][1] = fma2(as, b0.y, acc[r][1]);
                acc[r][2] = fma2(as, b1.x, acc[r][2]);
                acc[r][3] = fma2(as, b1.y, acc[r][3]);
            }
        }
    }
    float4 bv0 = *(const float4*)&bias[j0 + tx*8];
    float4 bv1 = *(const float4*)&bias[j0 + tx*8 + 4];
    float* od = out + (size_t)dir * M * ldw;
#pragma unroll
    for (int r = 0; r < 8; r++){
        float2 p0 = upk2(acc[r][0]), p1 = upk2(acc[r][1]);
        float2 p2 = upk2(acc[r][2]), p3 = upk2(acc[r][3]);
        float4 o0{p0.x + bv0.x, p0.y + bv0.y, p1.x + bv0.z, p1.y + bv0.w};
        float4 o1{p2.x + bv1.x, p2.y + bv1.y, p3.x + bv1.z, p3.y + bv1.w};
        size_t off = (size_t)(m0 + ty*8 + r) * ldw + j0 + tx*8;
        *(float4*)&od[off]     = o0;
        *(float4*)&od[off + 4] = o1;
    }
}

// ---------------------------------------------------------------------------
// GRU scan: persistent blocks, G sequences/block, h in smem [k][g].
// Thread j owns hidden unit j (gates r,z,n). Wh pre-packed as float4/k.
// grid = (NS/G)*2 (both dirs), 256 threads.
// ---------------------------------------------------------------------------
template<int T, int G>
__global__ __launch_bounds__(256) void gru_scan_kernel(
    const float* __restrict__ xg,   // [2][NS*T][768]
    float* __restrict__ hout,       // [NS*T][512]
    const float4* __restrict__ whp, // [2][256][256]
    const float* __restrict__ bhf, const float* __restrict__ bhb, int NS)
{
    constexpr int P = G / 2;
    __shared__ __align__(8) float sh[256][G];
    int j = threadIdx.x;
    int gpd = NS / G;
    int d  = blockIdx.x / gpd;
    int n0 = (blockIdx.x % gpd) * G;
    const float* bh = d ? bhb : bhf;
    const float4* Wp = whp + (size_t)d * 256 * 256;
    const float* xgd = xg + (size_t)d * NS * T * HD3;
    float bhr = bh[j], bhz = bh[256 + j], bhn = bh[512 + j];
#pragma unroll
    for (int g = 0; g < G; g++) sh[j][g] = 0.f;
    __syncthreads();

    for (int tt = 0; tt < T; tt++) {
        int t = d ? (T - 1 - tt) : tt;
        float xr[G], xz[G], xn[G];
#pragma unroll
        for (int g = 0; g < G; g++) {
            const float* xp = xgd + ((size_t)(n0 + g) * T + t) * HD3;
            xr[g] = xp[j]; xz[g] = xp[256 + j]; xn[g] = xp[512 + j];
        }
        ull ar[P], az[P], an[P];
#pragma unroll
        for (int p = 0; p < P; p++){
            ar[p] = pk2(bhr, bhr); az[p] = pk2(bhz, bhz); an[p] = pk2(bhn, bhn);
        }
        float4 w = Wp[j];
#pragma unroll 8
        for (int k = 0; k < 256; k++) {
            float4 wnext = Wp[(size_t)(k + 1) * 256 + j];  // pad row beyond end
            ull wr2 = pk2(w.x, w.x), wz2 = pk2(w.y, w.y), wn2 = pk2(w.z, w.z);
#pragma unroll
            for (int p = 0; p < P; p++){
                ull h2 = *(const ull*)&sh[k][2*p];
                ar[p] = fma2(wr2, h2, ar[p]);
                az[p] = fma2(wz2, h2, az[p]);
                an[p] = fma2(wn2, h2, an[p]);
            }
            w = wnext;
        }
        float hnew[G];
#pragma unroll
        for (int p = 0; p < P; p++){
            float2 fr = upk2(ar[p]), fz = upk2(az[p]), fn = upk2(an[p]);
            int g0 = 2*p, g1 = 2*p + 1;
            {
                float r = fsig(xr[g0] + fr.x), z = fsig(xz[g0] + fz.x);
                float n = ftanh(xn[g0] + r * fn.x);
                hnew[g0] = (1.f - z) * n + z * sh[j][g0];
            }
            {
                float r = fsig(xr[g1] + fr.y), z = fsig(xz[g1] + fz.y);
                float n = ftanh(xn[g1] + r * fn.y);
                hnew[g1] = (1.f - z) * n + z * sh[j][g1];
            }
        }
        __syncthreads();
#pragma unroll
        for (int g = 0; g < G; g++){
            sh[j][g] = hnew[g];
            hout[((size_t)(n0 + g) * T + t) * HD2 + d * 256 + j] = hnew[g];
        }
        __syncthreads();
    }
}

// ---------------------------------------------------------------------------
// Attention epilogue: per-sequence block. score=tanh(rep)@ctx -> sparsemax ->
// weighted sum of h. FINAL adds doc @ outW + outb.
// ---------------------------------------------------------------------------
template<int T, bool FINAL>
__global__ __launch_bounds__(256) void attn_epi_kernel(
    const float* __restrict__ rep,    // [nseq*T][512] (pre-tanh)
    const float* __restrict__ h,      // [nseq*T][512]
    const float* __restrict__ ctx,    // [512]
    float* __restrict__ outv,         // [nseq][512]  (!FINAL)
    const float* __restrict__ outW,   // [512][10]    (FINAL)
    const float* __restrict__ outb,   // [10]
    float* __restrict__ outFinal)     // [NDOC][10]
{
    __shared__ float sScore[T], sX[T], sSrt[T], sAtt[T];
    __shared__ float sTau, sMax;
    __shared__ float sDoc[512];
    int tid = threadIdx.x, lane = tid & 31, w = tid >> 5;
    int n = blockIdx.x;
    const float* rbase = rep + (size_t)n * T * HD2;
    const float* hbase = h   + (size_t)n * T * HD2;

    // scores
    for (int t = w; t < T; t += 8){
        float s = 0.f;
        for (int jj = lane * 4; jj < 512; jj += 128){
            float4 r4 = *(const float4*)&rbase[(size_t)t * HD2 + jj];
            float4 c4 = *(const float4*)&ctx[jj];
            s += ftanh(r4.x)*c4.x + ftanh(r4.y)*c4.y + ftanh(r4.z)*c4.z + ftanh(r4.w)*c4.w;
        }
        for (int o = 16; o; o >>= 1) s += __shfl_xor_sync(0xffffffffu, s, o);
        if (!lane) sScore[t] = s;
    }
    __syncthreads();

    // sparsemax (exact)
    if (tid == 0) {
        float mx = sScore[0];
        for (int t = 1; t < T; t++) mx = fmaxf(mx, sScore[t]);
        sMax = mx;
    }
    __syncthreads();
    if (tid < T) {
        float x = sScore[tid] - sMax;
        sX[tid] = x;
        int rank = 0;
        for (int u = 0; u < T; u++){
            float xu = sScore[u] - sMax;
            if (xu > x || (xu == x && u < tid)) rank++;
        }
        sSrt[rank] = x;
    }
    __syncthreads();
    if (tid == 0) {
        float cs = -1.f; int supp = 0; float csAt = 0.f;
        for (int k = 0; k < T; k++){
            cs += sSrt[k];
            if ((float)(k + 1) * sSrt[k] > cs) { supp = k + 1; csAt = cs; }
        }
        sTau = csAt / (float)supp;
    }
    __syncthreads();
    if (tid < T) sAtt[tid] = fmaxf(sX[tid] - sTau, 0.f);
    __syncthreads();

    // weighted sum over timesteps
    {
        int jj = tid * 2;
        float ax = 0.f, ay = 0.f;
#pragma unroll 8
        for (int t = 0; t < T; t++){
            float2 hv = *(const float2*)&hbase[(size_t)t * HD2 + jj];
            float a = sAtt[t];
            ax += a * hv.x; ay += a * hv.y;
        }
        if (FINAL){ sDoc[jj] = ax; sDoc[jj + 1] = ay; }
        else { float2 o{ax, ay}; *(float2*)&outv[(size_t)n * HD2 + jj] = o; }
    }
    if (FINAL) {
        __syncthreads();
        if (tid < 10) {
            float s = outb[tid];
            for (int jj2 = 0; jj2 < 512; jj2++) s += sDoc[jj2] * outW[jj2 * 10 + tid];
            outFinal[n * 10 + tid] = s;
        }
    }
}

extern "C" void kernel_launch(void* const* d_in, const int* in_sizes, int n_in,
                              void* d_out, int out_size) {
    const int*   tokens  = (const int*)  d_in[0];
    const float* emb     = (const float*)d_in[1];
    const float* w_Wx_f  = (const float*)d_in[2];
    const float* w_Wh_f  = (const float*)d_in[3];
    const float* w_bx_f  = (const float*)d_in[4];
    const float* w_bh_f  = (const float*)d_in[5];
    const float* w_Wx_b  = (const float*)d_in[6];
    const float* w_Wh_b  = (const float*)d_in[7];
    const float* w_bx_b  = (const float*)d_in[8];
    const float* w_bh_b  = (const float*)d_in[9];
    const float* w_lin_W = (const float*)d_in[10];
    const float* w_lin_b = (const float*)d_in[11];
    const float* w_ctx   = (const float*)d_in[12];
    const float* s_Wx_f  = (const float*)d_in[13];
    const float* s_Wh_f  = (const float*)d_in[14];
    const float* s_bx_f  = (const float*)d_in[15];
    const float* s_bh_f  = (const float*)d_in[16];
    const float* s_Wx_b  = (const float*)d_in[17];
    const float* s_Wh_b  = (const float*)d_in[18];
    const float* s_bx_b  = (const float*)d_in[19];
    const float* s_bh_b  = (const float*)d_in[20];
    const float* s_lin_W = (const float*)d_in[21];
    const float* s_lin_b = (const float*)d_in[22];
    const float* s_ctx   = (const float*)d_in[23];
    const float* out_W   = (const float*)d_in[24];
    const float* out_b   = (const float*)d_in[25];
    float* out = (float*)d_out;

    float *p_xg, *p_h, *p_sents, *p_xg2, *p_h2;
    float4 *p_whp, *p_whp2;
    cudaGetSymbolAddress((void**)&p_xg,   g_xg);
    cudaGetSymbolAddress((void**)&p_h,    g_h);
    cudaGetSymbolAddress((void**)&p_sents,g_sents);
    cudaGetSymbolAddress((void**)&p_xg2,  g_xg2);
    cudaGetSymbolAddress((void**)&p_h2,   g_h2);
    cudaGetSymbolAddress((void**)&p_whp,  g_whp);
    cudaGetSymbolAddress((void**)&p_whp2, g_whp2);

    // 0. repack recurrent weights
    repack_wh_kernel<<<dim3(256,2), 256>>>(w_Wh_f, w_Wh_b, p_whp);
    repack_wh_kernel<<<dim3(256,2), 256>>>(s_Wh_f, s_Wh_b, p_whp2);
    // 1. word input gates (embedding gather fused), both dirs
    gemm128_kernel<<<dim3(MWORD/128, 12), 256>>>(
        emb, tokens, EDIM, w_Wx_f, w_Wx_b, w_bx_f, w_bx_b, p_xg, MWORD, 6);
    // 2. word BiGRU scan
    gru_scan_kernel<TW, 16><<<(NWSEQ/16)*2, 256>>>(
        p_xg, p_h, p_whp, w_bh_f, w_bh_b, NWSEQ);
    // 3. word rep GEMM: rep = h @ linW + b   (reuse g_xg as scratch)
    gemm128_kernel<<<dim3(MWORD/128, 4), 256>>>(
        p_h, nullptr, HD2, w_lin_W, w_lin_W, w_lin_b, w_lin_b, p_xg, MWORD, 4);
    // 4. word attention epilogue -> sentence vectors
    attn_epi_kernel<TW, false><<<NWSEQ, 256>>>(
        p_xg, p_h, w_ctx, p_sents, nullptr, nullptr, nullptr);
    // 5. sentence input gates
    gemm128_kernel<<<dim3(MSENT/128, 12), 256>>>(
        p_sents, nullptr, HD2, s_Wx_f, s_Wx_b, s_bx_f, s_bx_b, p_xg2, MSENT, 6);
    // 6. sentence BiGRU scan
    gru_scan_kernel<TSENT, 2><<<(NDOC/2)*2, 256>>>(
        p_xg2, p_h2, p_whp2, s_bh_f, s_bh_b, NDOC);
    // 7. sentence rep GEMM (reuse g_xg2 as scratch)
    gemm128_kernel<<<dim3(MSENT/128, 4), 256>>>(
        p_h2, nullptr, HD2, s_lin_W, s_lin_W, s_lin_b, s_lin_b, p_xg2, MSENT, 4);
    // 8. sentence attention + final classifier
    attn_epi_kernel<TSENT, true><<<NDOC, 256>>>(
        p_xg2, p_h2, s_ctx, nullptr, out_W, out_b, out);
}

// round 4
// speedup vs baseline: 1.5305x; 1.5305x over previous
#include <cuda_runtime.h>
#include <cuda_bf16.h>
#include <cstdint>
#include <cstddef>

#define NWSEQ 1024
#define TW    64
#define MWORD (NWSEQ*TW)
#define NDOC  32
#define TSENT 32
#define MSENT (NDOC*TSENT)
#define HD2   512
#define HD3   768
#define EDIM  200

typedef unsigned long long ull;

// scratch (device globals; allocation-free rule)
__device__ float g_xg [2ull*MWORD*HD3];     // word input gates; later partial scores
__device__ float g_h  [(size_t)MWORD*HD2];  // word BiGRU hidden
__device__ float g_sents[(size_t)MSENT*HD2];
__device__ float g_xg2[2ull*MSENT*HD3];     // sentence input gates; later partial scores
__device__ float g_h2 [(size_t)MSENT*HD2];
__device__ float4 g_whp [2*256*256 + 256];  // repacked word Wh [dir][k][j]{r,z,n,0} + prefetch pad
__device__ float4 g_whp2[2*256*256 + 256];

__device__ __forceinline__ ull pk2(float lo, float hi){
    ull r; asm("mov.b64 %0, {%1,%2};" : "=l"(r) : "f"(lo), "f"(hi)); return r;
}
__device__ __forceinline__ float2 upk2(ull v){
    float2 f; asm("mov.b64 {%0,%1}, %2;" : "=f"(f.x), "=f"(f.y) : "l"(v)); return f;
}
__device__ __forceinline__ ull fma2(ull a, ull b, ull c){
    ull d; asm("fma.rn.f32x2 %0, %1, %2, %3;" : "=l"(d) : "l"(a), "l"(b), "l"(c)); return d;
}
__device__ __forceinline__ float fsig(float x){ return 1.0f/(1.0f + __expf(-x)); }
__device__ __forceinline__ float ftanh(float x){ return 1.0f - 2.0f/(__expf(2.0f*x) + 1.0f); }

// ---------------------------------------------------------------------------
// Repack Wh [256][768] -> float4[dir][k][j] = {Wr, Wz, Wn, 0}
// ---------------------------------------------------------------------------
__global__ void repack_wh_kernel(const float* __restrict__ Whf,
                                 const float* __restrict__ Whb,
                                 float4* __restrict__ whp){
    int k = blockIdx.x, d = blockIdx.y, j = threadIdx.x;
    const float* Wh = d ? Whb : Whf;
    float4 v;
    v.x = Wh[(size_t)k*HD3 + j];
    v.y = Wh[(size_t)k*HD3 + 256 + j];
    v.z = Wh[(size_t)k*HD3 + 512 + j];
    v.w = 0.f;
    whp[((size_t)d*256 + k)*256 + j] = v;
}

// ---------------------------------------------------------------------------
// GEMM, 128x64 tile, BK=8, 8x4 micro, double-buffered smem, 256 thr, 2 blk/SM.
//  SCORE=0: out[dir][m][j] = A[row(m)] @ W_dir + bias_dir   (ldw = nyPerDir*64)
//  SCORE=1: out[jb*M + m] = sum_j tanh((A@W+b)[m][j]) * ctx[j]  over this tile's 64 j
// grid = (M/128, (SCORE?1:2)*nyPerDir)
// ---------------------------------------------------------------------------
template<bool SCORE>
__global__ __launch_bounds__(256,2) void gemm_tile_kernel(
    const float* __restrict__ A, const int* __restrict__ gather, int K,
    const float* __restrict__ Wf, const float* __restrict__ Wb,
    const float* __restrict__ bf, const float* __restrict__ bb,
    const float* __restrict__ ctx,
    float* __restrict__ out, int M, int nyPerDir)
{
    __shared__ __align__(16) float sA[2][8][132];
    __shared__ __align__(16) float sB[2][8][64];
    int tid = threadIdx.x;
    int tx = tid & 15, ty = tid >> 4;
    int m0 = blockIdx.x * 128;
    int dir = blockIdx.y / nyPerDir;
    int jb  = blockIdx.y % nyPerDir;
    int j0  = jb * 64;
    int ldw = nyPerDir * 64;
    const float* W    = dir ? Wb : Wf;
    const float* bias = dir ? bb : bf;

    int kA = tid & 7, mA = tid >> 3;
    const float* arow[4];
#pragma unroll
    for (int i = 0; i < 4; i++){
        int r = m0 + mA + 32*i;
        arow[i] = A + (size_t)(gather ? gather[r] : r) * K;
    }
    int kB = tid >> 5, jB = (tid & 31) * 2;

    ull acc[8][2];
#pragma unroll
    for (int r = 0; r < 8; r++){ acc[r][0] = 0ull; acc[r][1] = 0ull; }

    float ra[4]; float2 rb;
#pragma unroll
    for (int i = 0; i < 4; i++) ra[i] = arow[i][kA];
    rb = *(const float2*)&W[(size_t)kB * ldw + j0 + jB];
#pragma unroll
    for (int i = 0; i < 4; i++) sA[0][kA][mA + 32*i] = ra[i];
    *(float2*)&sB[0][kB][jB] = rb;
    __syncthreads();

    int nt = K / 8;
    for (int t = 0; t < nt; t++) {
        int cur = t & 1;
        if (t + 1 < nt) {
            int k0 = (t + 1) * 8;
#pragma unroll
            for (int i = 0; i < 4; i++) ra[i] = arow[i][k0 + kA];
            rb = *(const float2*)&W[(size_t)(k0 + kB) * ldw + j0 + jB];
        }
#pragma unroll
        for (int kk = 0; kk < 8; kk++){
            float4 a0 = *(const float4*)&sA[cur][kk][ty*8];
            float4 a1 = *(const float4*)&sA[cur][kk][ty*8 + 4];
            ulonglong2 b = *(const ulonglong2*)&sB[cur][kk][tx*4];
            float av[8] = {a0.x,a0.y,a0.z,a0.w,a1.x,a1.y,a1.z,a1.w};
#pragma unroll
            for (int r = 0; r < 8; r++){
                ull as = pk2(av[r], av[r]);
                acc[r][0] = fma2(as, b.x, acc[r][0]);
                acc[r][1] = fma2(as, b.y, acc[r][1]);
            }
        }
        if (t + 1 < nt) {
            int nxt = cur ^ 1;
#pragma unroll
            for (int i = 0; i < 4; i++) sA[nxt][kA][mA + 32*i] = ra[i];
            *(float2*)&sB[nxt][kB][jB] = rb;
            __syncthreads();
        }
    }

    float4 bv = *(const float4*)&bias[j0 + tx*4];
    if (!SCORE) {
        float* od = out + (size_t)dir * M * ldw;
#pragma unroll
        for (int r = 0; r < 8; r++){
            float2 p0 = upk2(acc[r][0]), p1 = upk2(acc[r][1]);
            float4 o{p0.x + bv.x, p0.y + bv.y, p1.x + bv.z, p1.y + bv.w};
            *(float4*)&od[(size_t)(m0 + ty*8 + r) * ldw + j0 + tx*4] = o;
        }
    } else {
        float4 c4 = *(const float4*)&ctx[j0 + tx*4];
#pragma unroll
        for (int r = 0; r < 8; r++){
            float2 p0 = upk2(acc[r][0]), p1 = upk2(acc[r][1]);
            float s = ftanh(p0.x + bv.x)*c4.x + ftanh(p0.y + bv.y)*c4.y
                    + ftanh(p1.x + bv.z)*c4.z + ftanh(p1.y + bv.w)*c4.w;
#pragma unroll
            for (int o = 8; o; o >>= 1) s += __shfl_xor_sync(0xffffffffu, s, o);
            if (tx == 0) out[(size_t)jb * M + m0 + ty*8 + r] = s;
        }
    }
}

// ---------------------------------------------------------------------------
// GRU scan: G seqs/block, h ping-pong in smem [buf][k][g], h_prev in regs.
// Thread j owns hidden unit j. One __syncthreads per step.
// grid = (NS/G)*2, 256 threads, 2 blocks/SM.
// ---------------------------------------------------------------------------
template<int T, int G>
__global__ __launch_bounds__(256,2) void gru_scan_kernel(
    const float* __restrict__ xg,   // [2][NS*T][768]
    float* __restrict__ hout,       // [NS*T][512]
    const float4* __restrict__ whp, // [2][256][256]
    const float* __restrict__ bhf, const float* __restrict__ bhb, int NS)
{
    constexpr int P = G / 2;
    __shared__ __align__(16) float sh[2][256][G];
    int j = threadIdx.x;
    int gpd = NS / G;
    int d  = blockIdx.x / gpd;
    int n0 = (blockIdx.x % gpd) * G;
    const float* bh = d ? bhb : bhf;
    const float4* Wp = whp + (size_t)d * 256 * 256;
    const float* xgd = xg + (size_t)d * NS * T * HD3;
    float bhr = bh[j], bhz = bh[256 + j], bhn = bh[512 + j];
    float hprev[G];
#pragma unroll
    for (int g = 0; g < G; g++){ hprev[g] = 0.f; sh[0][j][g] = 0.f; }
    __syncthreads();

    int cur = 0;
    for (int tt = 0; tt < T; tt++) {
        int t = d ? (T - 1 - tt) : tt;
        float xr[G], xz[G], xn[G];
#pragma unroll
        for (int g = 0; g < G; g++) {
            const float* xp = xgd + ((size_t)(n0 + g) * T + t) * HD3;
            xr[g] = xp[j]; xz[g] = xp[256 + j]; xn[g] = xp[512 + j];
        }
        ull ar[P], az[P], an[P];
#pragma unroll
        for (int p = 0; p < P; p++){
            ar[p] = pk2(bhr, bhr); az[p] = pk2(bhz, bhz); an[p] = pk2(bhn, bhn);
        }
        float4 w = Wp[j];
#pragma unroll 8
        for (int k = 0; k < 256; k++) {
            float4 wnext = Wp[(size_t)(k + 1) * 256 + j];   // pad row beyond end
            ull wr2 = pk2(w.x, w.x), wz2 = pk2(w.y, w.y), wn2 = pk2(w.z, w.z);
#pragma unroll
            for (int p = 0; p < P; p++){
                ull h2 = *(const ull*)&sh[cur][k][2*p];
                ar[p] = fma2(wr2, h2, ar[p]);
                az[p] = fma2(wz2, h2, az[p]);
                an[p] = fma2(wn2, h2, an[p]);
            }
            w = wnext;
        }
        int nxt = cur ^ 1;
        float hnew[G];
#pragma unroll
        for (int p = 0; p < P; p++){
            float2 fr = upk2(ar[p]), fz = upk2(az[p]), fn = upk2(an[p]);
            int g0 = 2*p, g1 = 2*p + 1;
            {
                float r = fsig(xr[g0] + fr.x), z = fsig(xz[g0] + fz.x);
                float n = ftanh(xn[g0] + r * fn.x);
                hnew[g0] = (1.f - z) * n + z * hprev[g0];
            }
            {
                float r = fsig(xr[g1] + fr.y), z = fsig(xz[g1] + fz.y);
                float n = ftanh(xn[g1] + r * fn.y);
                hnew[g1] = (1.f - z) * n + z * hprev[g1];
            }
        }
#pragma unroll
        for (int g = 0; g < G; g++){
            hprev[g] = hnew[g];
            sh[nxt][j][g] = hnew[g];
            hout[((size_t)(n0 + g) * T + t) * HD2 + d * 256 + j] = hnew[g];
        }
        cur = nxt;
        __syncthreads();
    }
}

// ---------------------------------------------------------------------------
// Attention epilogue: sum partial scores -> sparsemax -> weighted sum of h.
// FINAL adds doc @ outW + outb.
// ---------------------------------------------------------------------------
template<int T, bool FINAL>
__global__ __launch_bounds__(256) void attn_epi_kernel(
    const float* __restrict__ part,   // [8][nseq*T] partial scores
    const float* __restrict__ h,      // [nseq*T][512]
    float* __restrict__ outv,         // [nseq][512]  (!FINAL)
    const float* __restrict__ outW,   // [512][10]    (FINAL)
    const float* __restrict__ outb,   // [10]
    float* __restrict__ outFinal,     // [NDOC][10]
    int Mtot)
{
    __shared__ float sScore[T], sX[T], sSrt[T], sAtt[T];
    __shared__ float sTau, sMax;
    __shared__ float sDoc[512];
    int tid = threadIdx.x;
    int n = blockIdx.x;
    const float* hbase = h + (size_t)n * T * HD2;

    if (tid < T) {
        float s = 0.f;
#pragma unroll
        for (int jb = 0; jb < 8; jb++) s += part[(size_t)jb * Mtot + n * T + tid];
        sScore[tid] = s;
    }
    __syncthreads();

    if (tid == 0) {
        float mx = sScore[0];
        for (int t = 1; t < T; t++) mx = fmaxf(mx, sScore[t]);
        sMax = mx;
    }
    __syncthreads();
    if (tid < T) {
        float x = sScore[tid] - sMax;
        sX[tid] = x;
        int rank = 0;
        for (int u = 0; u < T; u++){
            float xu = sScore[u] - sMax;
            if (xu > x || (xu == x && u < tid)) rank++;
        }
        sSrt[rank] = x;
    }
    __syncthreads();
    if (tid == 0) {
        float cs = -1.f; int supp = 0; float csAt = 0.f;
        for (int k = 0; k < T; k++){
            cs += sSrt[k];
            if ((float)(k + 1) * sSrt[k] > cs) { supp = k + 1; csAt = cs; }
        }
        sTau = csAt / (float)supp;
    }
    __syncthreads();
    if (tid < T) sAtt[tid] = fmaxf(sX[tid] - sTau, 0.f);
    __syncthreads();

    {
        int jj = tid * 2;
        float ax = 0.f, ay = 0.f;
#pragma unroll 8
        for (int t = 0; t < T; t++){
            float2 hv = *(const float2*)&hbase[(size_t)t * HD2 + jj];
            float a = sAtt[t];
            ax += a * hv.x; ay += a * hv.y;
        }
        if (FINAL){ sDoc[jj] = ax; sDoc[jj + 1] = ay; }
        else { float2 o{ax, ay}; *(float2*)&outv[(size_t)n * HD2 + jj] = o; }
    }
    if (FINAL) {
        __syncthreads();
        if (tid < 10) {
            float s = outb[tid];
            for (int jj2 = 0; jj2 < 512; jj2++) s += sDoc[jj2] * outW[jj2 * 10 + tid];
            outFinal[n * 10 + tid] = s;
        }
    }
}

extern "C" void kernel_launch(void* const* d_in, const int* in_sizes, int n_in,
                              void* d_out, int out_size) {
    const int*   tokens  = (const int*)  d_in[0];
    const float* emb     = (const float*)d_in[1];
    const float* w_Wx_f  = (const float*)d_in[2];
    const float* w_Wh_f  = (const float*)d_in[3];
    const float* w_bx_f  = (const float*)d_in[4];
    const float* w_bh_f  = (const float*)d_in[5];
    const float* w_Wx_b  = (const float*)d_in[6];
    const float* w_Wh_b  = (const float*)d_in[7];
    const float* w_bx_b  = (const float*)d_in[8];
    const float* w_bh_b  = (const float*)d_in[9];
    const float* w_lin_W = (const float*)d_in[10];
    const float* w_lin_b = (const float*)d_in[11];
    const float* w_ctx   = (const float*)d_in[12];
    const float* s_Wx_f  = (const float*)d_in[13];
    const float* s_Wh_f  = (const float*)d_in[14];
    const float* s_bx_f  = (const float*)d_in[15];
    const float* s_bh_f  = (const float*)d_in[16];
    const float* s_Wx_b  = (const float*)d_in[17];
    const float* s_Wh_b  = (const float*)d_in[18];
    const float* s_bx_b  = (const float*)d_in[19];
    const float* s_bh_b  = (const float*)d_in[20];
    const float* s_lin_W = (const float*)d_in[21];
    const float* s_lin_b = (const float*)d_in[22];
    const float* s_ctx   = (const float*)d_in[23];
    const float* out_W   = (const float*)d_in[24];
    const float* out_b   = (const float*)d_in[25];
    float* out = (float*)d_out;

    float *p_xg, *p_h, *p_sents, *p_xg2, *p_h2;
    float4 *p_whp, *p_whp2;
    cudaGetSymbolAddress((void**)&p_xg,   g_xg);
    cudaGetSymbolAddress((void**)&p_h,    g_h);
    cudaGetSymbolAddress((void**)&p_sents,g_sents);
    cudaGetSymbolAddress((void**)&p_xg2,  g_xg2);
    cudaGetSymbolAddress((void**)&p_h2,   g_h2);
    cudaGetSymbolAddress((void**)&p_whp,  g_whp);
    cudaGetSymbolAddress((void**)&p_whp2, g_whp2);

    // 0. repack recurrent weights
    repack_wh_kernel<<<dim3(256,2), 256>>>(w_Wh_f, w_Wh_b, p_whp);
    repack_wh_kernel<<<dim3(256,2), 256>>>(s_Wh_f, s_Wh_b, p_whp2);
    // 1. word input gates (embedding gather fused), both dirs
    gemm_tile_kernel<false><<<dim3(MWORD/128, 24), 256>>>(
        emb, tokens, EDIM, w_Wx_f, w_Wx_b, w_bx_f, w_bx_b, nullptr, p_xg, MWORD, 12);
    // 2. word BiGRU scan
    gru_scan_kernel<TW, 8><<<(NWSEQ/8)*2, 256>>>(
        p_xg, p_h, p_whp, w_bh_f, w_bh_b, NWSEQ);
    // 3. word rep GEMM fused into scores (partials into g_xg, rep never stored)
    gemm_tile_kernel<true><<<dim3(MWORD/128, 8), 256>>>(
        p_h, nullptr, HD2, w_lin_W, w_lin_W, w_lin_b, w_lin_b, w_ctx, p_xg, MWORD, 8);
    // 4. word attention epilogue -> sentence vectors
    attn_epi_kernel<TW, false><<<NWSEQ, 256>>>(
        p_xg, p_h, p_sents, nullptr, nullptr, nullptr, MWORD);
    // 5. sentence input gates
    gemm_tile_kernel<false><<<dim3(MSENT/128, 24), 256>>>(
        p_sents, nullptr, HD2, s_Wx_f, s_Wx_b, s_bx_f, s_bx_b, nullptr, p_xg2, MSENT, 12);
    // 6. sentence BiGRU scan
    gru_scan_kernel<TSENT, 2><<<(NDOC/2)*2, 256>>>(
        p_xg2, p_h2, p_whp2, s_bh_f, s_bh_b, NDOC);
    // 7. sentence rep+score GEMM (partials into g_xg2)
    gemm_tile_kernel<true><<<dim3(MSENT/128, 8), 256>>>(
        p_h2, nullptr, HD2, s_lin_W, s_lin_W, s_lin_b, s_lin_b, s_ctx, p_xg2, MSENT, 8);
    // 8. sentence attention + final classifier
    attn_epi_kernel<TSENT, true><<<NDOC, 256>>>(
        p_xg2, p_h2, nullptr, out_W, out_b, out, MSENT);
}